// round 4
// baseline (speedup 1.0000x reference)
#include <cuda_runtime.h>

#define THRESH 0.5f
#define ALPHA  0.1f

// B=64, N=16384, C=16 -> 1,048,576 rows of 16 fp32.
// One thread per row: 4 float4 loads from x + 4 from y, all independent
// (MLP=8, no cross-lane ops in the hot loop). Mask is thread-local.
// Per-instruction the warp strides 64B with 16B chunks; paired instructions
// consume complementary sector halves via L1, so DRAM traffic is exact.

static constexpr int C = 16;
static constexpr int THREADS = 256;
static constexpr int BLOCKS = 1184;     // 148 SMs * 8 blocks

__device__ float g_partials[BLOCKS];
__device__ unsigned int g_done = 0;     // self-resetting last-block ticket

__device__ __forceinline__ float sq4(float4 a, float4 b) {
    float d0 = b.x - a.x, d1 = b.y - a.y, d2 = b.z - a.z, d3 = b.w - a.w;
    return d0 * d0 + d1 * d1 + d2 * d2 + d3 * d3;
}

__global__ __launch_bounds__(THREADS) void mloss_kernel(
    const float* __restrict__ x,
    const float* __restrict__ y,
    float* __restrict__ out,
    int n_rows)
{
    const int g0 = blockIdx.x * THREADS + threadIdx.x;
    const int stride = gridDim.x * THREADS;

    float acc = 0.0f;

    for (int row = g0; row < n_rows; row += stride) {
        const float4* xp = reinterpret_cast<const float4*>(x) + row * 4;
        const float4* yp = reinterpret_cast<const float4*>(y) + row * 4;

        // 8 independent loads, front-batched by ptxas
        float4 xv0 = xp[0], xv1 = xp[1], xv2 = xp[2], xv3 = xp[3];
        float4 yv0 = yp[0], yv1 = yp[1], yv2 = yp[2], yv3 = yp[3];

        float sq = sq4(xv0, yv0) + sq4(xv1, yv1)
                 + sq4(xv2, yv2) + sq4(xv3, yv3);

        acc += (yv0.x > THRESH) ? sq : (ALPHA * xv0.x * xv0.x);
    }

    // ---- block reduction ----
    #pragma unroll
    for (int off = 16; off > 0; off >>= 1)
        acc += __shfl_xor_sync(0xFFFFFFFFu, acc, off);

    __shared__ float warp_sums[THREADS / 32];
    __shared__ bool is_last;
    const int lane = threadIdx.x & 31;
    const int wid  = threadIdx.x >> 5;
    if (lane == 0) warp_sums[wid] = acc;
    __syncthreads();

    if (wid == 0) {
        float v = (lane < THREADS / 32) ? warp_sums[lane] : 0.0f;
        #pragma unroll
        for (int off = 4; off > 0; off >>= 1)
            v += __shfl_xor_sync(0xFFFFFFFFu, v, off);
        if (lane == 0) {
            g_partials[blockIdx.x] = v;
            __threadfence();
            unsigned int t = atomicAdd(&g_done, 1u);
            is_last = (t == (unsigned int)gridDim.x - 1u);
        }
    }
    __syncthreads();

    // ---- last block: reduce 1184 partials -> out (plain store, no init needed)
    if (is_last) {
        float v = 0.0f;
        for (int i = threadIdx.x; i < gridDim.x; i += THREADS)
            v += g_partials[i];
        #pragma unroll
        for (int off = 16; off > 0; off >>= 1)
            v += __shfl_xor_sync(0xFFFFFFFFu, v, off);
        __syncthreads();                  // warp_sums reuse
        if (lane == 0) warp_sums[wid] = v;
        __syncthreads();
        if (wid == 0) {
            float t = (lane < THREADS / 32) ? warp_sums[lane] : 0.0f;
            #pragma unroll
            for (int off = 4; off > 0; off >>= 1)
                t += __shfl_xor_sync(0xFFFFFFFFu, t, off);
            if (lane == 0) {
                out[0] = t;
                g_done = 0;               // reset for next graph replay
            }
        }
    }
}

extern "C" void kernel_launch(void* const* d_in, const int* in_sizes, int n_in,
                              void* d_out, int out_size) {
    const float* x = (const float*)d_in[0];
    const float* y = (const float*)d_in[1];
    float* out = (float*)d_out;

    const int total = in_sizes[0];    // B*N*C = 16,777,216
    const int n_rows = total / C;

    mloss_kernel<<<BLOCKS, THREADS>>>(x, y, out, n_rows);
}

// round 5
// speedup vs baseline: 1.0900x; 1.0900x over previous
#include <cuda_runtime.h>

#define THRESH 0.5f
#define ALPHA  0.1f

// B=64, N=16384, C=16 -> 1,048,576 rows of 16 fp32 = 4,194,304 float4 slots.
// 4 lanes cooperate on one row (one float4 each) so every warp-level LDG.128
// covers 512 fully-contiguous bytes (R3-proven: L1 stays ~20%).
// Instead of reducing sq across the 4-lane group (R3: 2 shfls on the full
// FMA chain), each lane keeps its own partial and we broadcast ONLY the mask
// value y[row,0] from the group base lane (1 shfl, depends only on the y load).

static constexpr int C = 16;
static constexpr int THREADS = 256;
static constexpr int BLOCKS = 1184;     // 148 SMs * 8 blocks

__device__ float g_partials[BLOCKS];
__device__ unsigned int g_done = 0;     // self-resetting last-block ticket

__device__ __forceinline__ float slot_contrib(
    const float* __restrict__ x, const float* __restrict__ y,
    int slot, int q)
{
    const float4 xv = *(reinterpret_cast<const float4*>(x) + slot);
    const float4 yv = *(reinterpret_cast<const float4*>(y) + slot);

    // broadcast y[row,0] (held by lane with q==0) to the 4-lane group
    const float y0 = __shfl_sync(0xFFFFFFFFu, yv.x, 0, 4);

    float d0 = yv.x - xv.x;
    float d1 = yv.y - xv.y;
    float d2 = yv.z - xv.z;
    float d3 = yv.w - xv.w;
    float sq = d0 * d0 + d1 * d1 + d2 * d2 + d3 * d3;

    if (y0 > THRESH) {
        return sq;                       // every lane adds its own quarter
    } else {
        return (q == 0) ? (ALPHA * xv.x * xv.x) : 0.0f;
    }
}

__global__ __launch_bounds__(THREADS) void mloss_kernel(
    const float* __restrict__ x,
    const float* __restrict__ y,
    float* __restrict__ out,
    int n_slots)
{
    const int g0 = blockIdx.x * THREADS + threadIdx.x;
    const int stride = gridDim.x * THREADS;
    const int q = threadIdx.x & 3;       // stride % 4 == 0, so q is loop-invariant

    float acc = 0.0f;

    int slot = g0;
    for (; slot + stride < n_slots; slot += 2 * stride) {
        acc += slot_contrib(x, y, slot, q);
        acc += slot_contrib(x, y, slot + stride, q);
    }
    if (slot < n_slots) {
        acc += slot_contrib(x, y, slot, q);
    }

    // ---- block reduction ----
    #pragma unroll
    for (int off = 16; off > 0; off >>= 1)
        acc += __shfl_xor_sync(0xFFFFFFFFu, acc, off);

    __shared__ float warp_sums[THREADS / 32];
    __shared__ bool is_last;
    const int lane = threadIdx.x & 31;
    const int wid  = threadIdx.x >> 5;
    if (lane == 0) warp_sums[wid] = acc;
    __syncthreads();

    if (wid == 0) {
        float v = (lane < THREADS / 32) ? warp_sums[lane] : 0.0f;
        #pragma unroll
        for (int off = 4; off > 0; off >>= 1)
            v += __shfl_xor_sync(0xFFFFFFFFu, v, off);
        if (lane == 0) {
            g_partials[blockIdx.x] = v;
            __threadfence();
            unsigned int t = atomicAdd(&g_done, 1u);
            is_last = (t == (unsigned int)gridDim.x - 1u);
        }
    }
    __syncthreads();

    // ---- last block: reduce 1184 partials -> out (plain store, no init kernel)
    if (is_last) {
        float v = 0.0f;
        for (int i = threadIdx.x; i < gridDim.x; i += THREADS)
            v += g_partials[i];
        #pragma unroll
        for (int off = 16; off > 0; off >>= 1)
            v += __shfl_xor_sync(0xFFFFFFFFu, v, off);
        __syncthreads();                  // warp_sums reuse
        if (lane == 0) warp_sums[wid] = v;
        __syncthreads();
        if (wid == 0) {
            float t = (lane < THREADS / 32) ? warp_sums[lane] : 0.0f;
            #pragma unroll
            for (int off = 4; off > 0; off >>= 1)
                t += __shfl_xor_sync(0xFFFFFFFFu, t, off);
            if (lane == 0) {
                out[0] = t;
                g_done = 0;               // reset for next graph replay
            }
        }
    }
}

extern "C" void kernel_launch(void* const* d_in, const int* in_sizes, int n_in,
                              void* d_out, int out_size) {
    const float* x = (const float*)d_in[0];
    const float* y = (const float*)d_in[1];
    float* out = (float*)d_out;

    const int total = in_sizes[0];    // B*N*C = 16,777,216
    const int n_slots = total / 4;    // one float4 per slot

    mloss_kernel<<<BLOCKS, THREADS>>>(x, y, out, n_slots);
}